// round 14
// baseline (speedup 1.0000x reference)
#include <cuda_runtime.h>
#include <cstdint>

// Problem shape (fixed by the dataset)
#define Bc   8
#define Ac   16384
#define Sc   2048
#define Dc   512
#define OUTc 512
#define CH   16      // residues per pool block

// K-dimension permutation (within each 8-col group): old col c -> position
//   p(c) = (c & ~7) | ((c & 3) << 1) | ((c >> 2) & 1)
// so old pair (lc, lc+4) lands at adjacent positions (2lc, 2lc+1) -> LDS.64 frags.
__host__ __device__ __forceinline__ int kperm(int c) {
    return (c & ~7) | (((c & 3) << 1) | ((c >> 2) & 1));
}

// ---------------- scratch (device globals; no allocation allowed) ----------
__device__ float g_pooled[Bc * Sc * Dc];   // 32 MB pooled [B,S,D], tf32, k-permuted
__device__ float g_Wtf[OUTc * Dc];         // W tf32-rounded, k-permuted
__device__ float g_avgsum[Bc * Dc];        // per-protein sums (k-permuted space)
__device__ int   g_filled[Bc * Sc];
__device__ int   g_nfill[Bc];

// ---------------- helpers --------------------------------------------------
__device__ __forceinline__ float f2tf_f(float x) {
    uint32_t r;
    asm("cvt.rna.tf32.f32 %0, %1;" : "=r"(r) : "f"(x));
    return __uint_as_float(r);
}

#define MMA_TF32(c0, c1, c2, c3, a0, a1, a2, a3, b0, b1)                      \
    asm volatile(                                                             \
        "mma.sync.aligned.m16n8k8.row.col.f32.tf32.tf32.f32 "                 \
        "{%0,%1,%2,%3}, {%4,%5,%6,%7}, {%8,%9}, {%0,%1,%2,%3};"               \
        : "+f"(c0), "+f"(c1), "+f"(c2), "+f"(c3)                              \
        : "r"(a0), "r"(a1), "r"(a2), "r"(a3), "r"(b0), "r"(b1))

__device__ __forceinline__ void cp_async16cg(void* smem_dst, const void* gmem_src) {
    uint32_t dst = (uint32_t)__cvta_generic_to_shared(smem_dst);
    asm volatile("cp.async.cg.shared.global [%0], [%1], 16;" ::"r"(dst), "l"(gmem_src));
}

// ---------------- kernel 0: zero accumulators + convert W to tf32 ----------
__global__ void prep_kernel(const float* __restrict__ W) {
    int i = blockIdx.x * 256 + threadIdx.x;
    if (i < OUTc * Dc) {
        int o = i >> 9, k = i & 511;
        g_Wtf[(o << 9) + kperm(k)] = f2tf_f(W[i]);
    }
    if (i < Bc * Dc) g_avgsum[i] = 0.0f;
    if (i < Bc) g_nfill[i] = 0;
}

// ---------------- kernel 1: fused segment-mean pooling + avg accumulation --
__global__ void pool_kernel(const float* __restrict__ rep,
                            const int* __restrict__ ids,
                            const int* __restrict__ aa_len,
                            const int* __restrict__ seq_len) {
    const int blk = blockIdx.x;
    const int b = blk / (Sc / CH);
    const int s0 = (blk % (Sc / CH)) * CH;
    const int L = aa_len[b];
    const int SL = seq_len[b];
    const int* p = ids + b * Ac;

    __shared__ int bound[CH + 1];
    const int t = threadIdx.x;  // 128 threads x 4 cols = 512 cols

    if (t <= CH) {
        int target = s0 + t;
        int lo = 0, hi = L;
        while (lo < hi) { int mid = (lo + hi) >> 1; if (p[mid] < target) lo = mid + 1; else hi = mid; }
        bound[t] = lo;
    }
    __syncthreads();

    // permuted destination columns for this thread's old cols 4t..4t+3
    const int nc0 = kperm(4 * t + 0), nc1 = kperm(4 * t + 1);
    const int nc2 = kperm(4 * t + 2), nc3 = kperm(4 * t + 3);

    const float4* base = reinterpret_cast<const float4*>(rep) + (size_t)b * Ac * (Dc / 4);
    float4 avg = make_float4(0.f, 0.f, 0.f, 0.f);
    int nf_local = 0;

#pragma unroll 1
    for (int i = 0; i < CH; i++) {
        const int st = bound[i], en = bound[i + 1];
        float4 acc = make_float4(0.f, 0.f, 0.f, 0.f);
        int a = st;
        // 4-way unrolled: 4 outstanding float4 loads per warp -> higher MLP
        for (; a + 3 < en; a += 4) {
            float4 v0 = base[(size_t)(a + 0) * (Dc / 4) + t];
            float4 v1 = base[(size_t)(a + 1) * (Dc / 4) + t];
            float4 v2 = base[(size_t)(a + 2) * (Dc / 4) + t];
            float4 v3 = base[(size_t)(a + 3) * (Dc / 4) + t];
            acc.x += (v0.x + v1.x) + (v2.x + v3.x);
            acc.y += (v0.y + v1.y) + (v2.y + v3.y);
            acc.z += (v0.z + v1.z) + (v2.z + v3.z);
            acc.w += (v0.w + v1.w) + (v2.w + v3.w);
        }
        for (; a < en; a++) {
            float4 v0 = base[(size_t)a * (Dc / 4) + t];
            acc.x += v0.x; acc.y += v0.y; acc.z += v0.z; acc.w += v0.w;
        }
        const int cnt = en - st;
        const float inv = 1.0f / (float)(cnt > 0 ? cnt : 1);
        acc.x = f2tf_f(acc.x * inv); acc.y = f2tf_f(acc.y * inv);
        acc.z = f2tf_f(acc.z * inv); acc.w = f2tf_f(acc.w * inv);

        const int row = b * Sc + s0 + i;
        float* pr = g_pooled + (size_t)row * Dc;
        pr[nc0] = acc.x; pr[nc1] = acc.y; pr[nc2] = acc.z; pr[nc3] = acc.w;

        const bool fill = (cnt > 0) && (s0 + i < SL);
        if (fill) {
            avg.x += acc.x; avg.y += acc.y; avg.z += acc.z; avg.w += acc.w;
            nf_local++;
        }
        if (t == 0) g_filled[row] = fill ? 1 : 0;
    }

    atomicAdd(&g_avgsum[b * Dc + nc0], avg.x);
    atomicAdd(&g_avgsum[b * Dc + nc1], avg.y);
    atomicAdd(&g_avgsum[b * Dc + nc2], avg.z);
    atomicAdd(&g_avgsum[b * Dc + nc3], avg.w);
    if (t == 0) atomicAdd(&g_nfill[b], nf_local);
}

// ---------------- kernel 2: GEMM out = pooled @ W^T + bias (tf32 mma) ------
// M=16384, N=512, K=512. BM=128, BN=64, BK=16, 3-stage, 8 warps (256 thr),
// warp tile 32x32 (4x2 grid). Reg cap 64 + smem 55.3KB -> 4 CTAs/SM,
// 32 warps/SM. Unfilled rows are zero in g_pooled -> fixed up post-GEMM.
#define BM 128
#define BN 64
#define BK 16
#define PADK 24     // conflict-free for LDS.64 fragment reads (verified per-phase)
#define STG 3
#define GEMM_THREADS 256
#define SMEM_BYTES (STG * (BM + BN) * PADK * 4)

__global__ __launch_bounds__(GEMM_THREADS, 4)
void gemm_kernel(const float* __restrict__ bias, float* __restrict__ out) {
    extern __shared__ float smem[];
    float* AsBase = smem;                         // [STG][BM][PADK]
    float* BsBase = smem + STG * BM * PADK;       // [STG][BN][PADK]

    const int tid = threadIdx.x;
    const int bm = blockIdx.x, bn = blockIdx.y;

    const float* Aori = g_pooled + (size_t)bm * BM * Dc;
    const float* Bori = g_Wtf + (size_t)bn * BN * Dc;

    const int warp = tid >> 5, lane = tid & 31;
    const int wm = warp >> 1, wn = warp & 1;      // 4 x 2 warp grid
    const int m_off = wm * 32, n_off = wn * 32;   // 32x32 warp tile
    const int lr = lane >> 2, lc = lane & 3;

    float c[2][4][4];
#pragma unroll
    for (int mi = 0; mi < 2; mi++)
#pragma unroll
        for (int ni = 0; ni < 4; ni++)
#pragma unroll
            for (int j = 0; j < 4; j++) c[mi][ni][j] = 0.f;

    // A: 128 rows x 4 float4 = 512 chunks -> 2/thread; B: 64 x 4 = 256 -> 1.
    const int a_row = tid >> 2, a_c4 = tid & 3;
    auto load_tile = [&](int kt, int st) {
        const int k0 = kt * BK;
        float* A = AsBase + st * BM * PADK;
        float* B = BsBase + st * BN * PADK;
        cp_async16cg(A + a_row * PADK + a_c4 * 4,
                     Aori + (size_t)a_row * Dc + k0 + a_c4 * 4);
        cp_async16cg(A + (a_row + 64) * PADK + a_c4 * 4,
                     Aori + (size_t)(a_row + 64) * Dc + k0 + a_c4 * 4);
        cp_async16cg(B + a_row * PADK + a_c4 * 4,
                     Bori + (size_t)a_row * Dc + k0 + a_c4 * 4);
        asm volatile("cp.async.commit_group;");
    };

    const int KT = Dc / BK;  // 32
    load_tile(0, 0);
    load_tile(1, 1);

    for (int kt = 0; kt < KT; kt++) {
        asm volatile("cp.async.wait_group 1;");
        __syncthreads();
        if (kt + 2 < KT) load_tile(kt + 2, (kt + 2) % STG);

        const float* A = AsBase + (kt % STG) * BM * PADK;
        const float* B = BsBase + (kt % STG) * BN * PADK;

#pragma unroll
        for (int ks = 0; ks < 2; ks++) {
            const int k0 = ks * 8 + 2 * lc;
            float2 alo[2], ahi[2], bv[4];
#pragma unroll
            for (int mi = 0; mi < 2; mi++) {
                const int r0 = m_off + mi * 16 + lr;
                alo[mi] = *reinterpret_cast<const float2*>(A + r0 * PADK + k0);
                ahi[mi] = *reinterpret_cast<const float2*>(A + (r0 + 8) * PADK + k0);
            }
#pragma unroll
            for (int ni = 0; ni < 4; ni++) {
                const int r0 = n_off + ni * 8 + lr;
                bv[ni] = *reinterpret_cast<const float2*>(B + r0 * PADK + k0);
            }
#pragma unroll
            for (int mi = 0; mi < 2; mi++)
#pragma unroll
                for (int ni = 0; ni < 4; ni++) {
                    MMA_TF32(c[mi][ni][0], c[mi][ni][1], c[mi][ni][2], c[mi][ni][3],
                             __float_as_uint(alo[mi].x), __float_as_uint(ahi[mi].x),
                             __float_as_uint(alo[mi].y), __float_as_uint(ahi[mi].y),
                             __float_as_uint(bv[ni].x), __float_as_uint(bv[ni].y));
                }
        }
        // no trailing sync — STG=3: the stage written by iteration kt+1's load
        // ((kt+3)%3) was consumed in iteration kt-1, ordered by the top barrier.
    }

    // epilogue: + bias, write fp32
    const int row_base = bm * BM + m_off;
    const int col_base = bn * BN + n_off;
#pragma unroll
    for (int mi = 0; mi < 2; mi++) {
#pragma unroll
        for (int ni = 0; ni < 4; ni++) {
            int r0 = row_base + mi * 16 + lr;
            int col = col_base + ni * 8 + 2 * lc;
            float b0 = bias[col], b1 = bias[col + 1];
            float2 v0 = make_float2(c[mi][ni][0] + b0, c[mi][ni][1] + b1);
            float2 v1 = make_float2(c[mi][ni][2] + b0, c[mi][ni][3] + b1);
            *reinterpret_cast<float2*>(out + (size_t)r0 * OUTc + col) = v0;
            *reinterpret_cast<float2*>(out + (size_t)(r0 + 8) * OUTc + col) = v1;
        }
    }
}

// ---------------- kernel 3: fixup unfilled in-range rows in OUT ------------
// out[row] = (avgsum[b]/nfill) @ W^T + bias, fp32. ~1 row per protein.
__global__ void fixup_kernel(const int* __restrict__ seq_len,
                             const float* __restrict__ bias,
                             float* __restrict__ out) {
    const int b = blockIdx.x;
    const int SL = seq_len[b];
    const int t = threadIdx.x;  // 256
    __shared__ float av[Dc];
    __shared__ int rows[256];
    __shared__ int nr;

    const int nf = g_nfill[b];
    const float inv = 1.0f / (float)(nf > 0 ? nf : 1);
    for (int i = t; i < Dc; i += 256) av[i] = g_avgsum[b * Dc + i] * inv;

    for (int tile = 0; tile < Sc; tile += 256) {
        if (t == 0) nr = 0;
        __syncthreads();
        const int s = tile + t;
        if (!g_filled[b * Sc + s] && s < SL) rows[atomicAdd(&nr, 1)] = s;
        __syncthreads();
        for (int i = 0; i < nr; i++) {
            const int r = b * Sc + rows[i];
            int o = t;
#pragma unroll
            for (int h = 0; h < 2; h++, o += 256) {
                const float* w = g_Wtf + (size_t)o * Dc;  // both sides k-permuted
                float acc = 0.f;
                for (int k = 0; k < Dc; k++) acc += av[k] * w[k];
                out[(size_t)r * OUTc + o] = acc + bias[o];
            }
        }
        __syncthreads();
    }
}

// ---------------- launcher -------------------------------------------------
extern "C" void kernel_launch(void* const* d_in, const int* in_sizes, int n_in,
                              void* d_out, int out_size) {
    const float* rep     = (const float*)d_in[0];
    const int*   ids     = (const int*)d_in[1];
    const int*   aa_len  = (const int*)d_in[2];
    const int*   seq_len = (const int*)d_in[3];
    const float* Wm      = (const float*)d_in[4];
    const float* bias    = (const float*)d_in[5];
    float*       out     = (float*)d_out;

    static bool attr_done = false;
    if (!attr_done) {
        cudaFuncSetAttribute(gemm_kernel, cudaFuncAttributeMaxDynamicSharedMemorySize,
                             SMEM_BYTES);
        attr_done = true;
    }

    prep_kernel<<<(OUTc * Dc + 255) / 256, 256>>>(Wm);
    pool_kernel<<<Bc * (Sc / CH), 128>>>(rep, ids, aa_len, seq_len);
    dim3 grid(Bc * Sc / BM, OUTc / BN);
    gemm_kernel<<<grid, GEMM_THREADS, SMEM_BYTES>>>(bias, out);
    fixup_kernel<<<Bc, 256>>>(seq_len, bias, out);
}

// round 15
// speedup vs baseline: 3.0878x; 3.0878x over previous
#include <cuda_runtime.h>
#include <cstdint>

// Problem shape (fixed by the dataset)
#define Bc   8
#define Ac   16384
#define Sc   2048
#define Dc   512
#define OUTc 512
#define CH   16      // residues per pool block

// K-dimension permutation (within each 8-col group): old col c -> position
//   p(c) = (c & ~7) | ((c & 3) << 1) | ((c >> 2) & 1)
// so old pair (lc, lc+4) lands at adjacent positions (2lc, 2lc+1) -> LDS.64 frags.
__host__ __device__ __forceinline__ int kperm(int c) {
    return (c & ~7) | (((c & 3) << 1) | ((c >> 2) & 1));
}

// ---------------- scratch (device globals; no allocation allowed) ----------
__device__ float g_pooled[Bc * Sc * Dc];   // 32 MB pooled [B,S,D], tf32, k-permuted
__device__ float g_Wtf[OUTc * Dc];         // W tf32-rounded, k-permuted
__device__ float g_avgsum[Bc * Dc];        // per-protein sums (k-permuted space)
__device__ int   g_filled[Bc * Sc];
__device__ int   g_nfill[Bc];

// ---------------- helpers --------------------------------------------------
__device__ __forceinline__ float f2tf_f(float x) {
    uint32_t r;
    asm("cvt.rna.tf32.f32 %0, %1;" : "=r"(r) : "f"(x));
    return __uint_as_float(r);
}

#define MMA_TF32(c0, c1, c2, c3, a0, a1, a2, a3, b0, b1)                      \
    asm volatile(                                                             \
        "mma.sync.aligned.m16n8k8.row.col.f32.tf32.tf32.f32 "                 \
        "{%0,%1,%2,%3}, {%4,%5,%6,%7}, {%8,%9}, {%0,%1,%2,%3};"               \
        : "+f"(c0), "+f"(c1), "+f"(c2), "+f"(c3)                              \
        : "r"(a0), "r"(a1), "r"(a2), "r"(a3), "r"(b0), "r"(b1))

__device__ __forceinline__ void cp_async16cg(void* smem_dst, const void* gmem_src) {
    uint32_t dst = (uint32_t)__cvta_generic_to_shared(smem_dst);
    asm volatile("cp.async.cg.shared.global [%0], [%1], 16;" ::"r"(dst), "l"(gmem_src));
}

// ---------------- kernel 0: zero accumulators + convert W to tf32 ----------
__global__ void prep_kernel(const float* __restrict__ W) {
    int i = blockIdx.x * 256 + threadIdx.x;
    if (i < OUTc * Dc) {
        int o = i >> 9, k = i & 511;
        g_Wtf[(o << 9) + kperm(k)] = f2tf_f(W[i]);
    }
    if (i < Bc * Dc) g_avgsum[i] = 0.0f;
    if (i < Bc) g_nfill[i] = 0;
}

// ---------------- kernel 1: fused segment-mean pooling + avg accumulation --
__global__ void pool_kernel(const float* __restrict__ rep,
                            const int* __restrict__ ids,
                            const int* __restrict__ aa_len,
                            const int* __restrict__ seq_len) {
    const int blk = blockIdx.x;
    const int b = blk / (Sc / CH);
    const int s0 = (blk % (Sc / CH)) * CH;
    const int L = aa_len[b];
    const int SL = seq_len[b];
    const int* p = ids + b * Ac;

    __shared__ int bound[CH + 1];
    const int t = threadIdx.x;  // 128 threads x 4 cols = 512 cols

    if (t <= CH) {
        int target = s0 + t;
        int lo = 0, hi = L;
        while (lo < hi) { int mid = (lo + hi) >> 1; if (p[mid] < target) lo = mid + 1; else hi = mid; }
        bound[t] = lo;
    }
    __syncthreads();

    // permuted destination columns for this thread's old cols 4t..4t+3
    const int nc0 = kperm(4 * t + 0), nc1 = kperm(4 * t + 1);
    const int nc2 = kperm(4 * t + 2), nc3 = kperm(4 * t + 3);

    const float4* base = reinterpret_cast<const float4*>(rep) + (size_t)b * Ac * (Dc / 4);
    float4 avg = make_float4(0.f, 0.f, 0.f, 0.f);
    int nf_local = 0;

#pragma unroll 1
    for (int i = 0; i < CH; i++) {
        const int st = bound[i], en = bound[i + 1];
        float4 acc = make_float4(0.f, 0.f, 0.f, 0.f);
        int a = st;
        // 4-way unrolled: 4 outstanding float4 loads per warp -> higher MLP
        for (; a + 3 < en; a += 4) {
            float4 v0 = base[(size_t)(a + 0) * (Dc / 4) + t];
            float4 v1 = base[(size_t)(a + 1) * (Dc / 4) + t];
            float4 v2 = base[(size_t)(a + 2) * (Dc / 4) + t];
            float4 v3 = base[(size_t)(a + 3) * (Dc / 4) + t];
            acc.x += (v0.x + v1.x) + (v2.x + v3.x);
            acc.y += (v0.y + v1.y) + (v2.y + v3.y);
            acc.z += (v0.z + v1.z) + (v2.z + v3.z);
            acc.w += (v0.w + v1.w) + (v2.w + v3.w);
        }
        for (; a < en; a++) {
            float4 v0 = base[(size_t)a * (Dc / 4) + t];
            acc.x += v0.x; acc.y += v0.y; acc.z += v0.z; acc.w += v0.w;
        }
        const int cnt = en - st;
        const float inv = 1.0f / (float)(cnt > 0 ? cnt : 1);
        acc.x = f2tf_f(acc.x * inv); acc.y = f2tf_f(acc.y * inv);
        acc.z = f2tf_f(acc.z * inv); acc.w = f2tf_f(acc.w * inv);

        const int row = b * Sc + s0 + i;
        float* pr = g_pooled + (size_t)row * Dc;
        pr[nc0] = acc.x; pr[nc1] = acc.y; pr[nc2] = acc.z; pr[nc3] = acc.w;

        const bool fill = (cnt > 0) && (s0 + i < SL);
        if (fill) {
            avg.x += acc.x; avg.y += acc.y; avg.z += acc.z; avg.w += acc.w;
            nf_local++;
        }
        if (t == 0) g_filled[row] = fill ? 1 : 0;
    }

    atomicAdd(&g_avgsum[b * Dc + nc0], avg.x);
    atomicAdd(&g_avgsum[b * Dc + nc1], avg.y);
    atomicAdd(&g_avgsum[b * Dc + nc2], avg.z);
    atomicAdd(&g_avgsum[b * Dc + nc3], avg.w);
    if (t == 0) atomicAdd(&g_nfill[b], nf_local);
}

// ---------------- kernel 2: fill unfilled in-range rows with protein avg ---
// avgsum and pooled are both in permuted space -> linear float4 copy is fine.
__global__ void fill_kernel(const int* __restrict__ seq_len) {
    __shared__ int rows[128];
    __shared__ int nr;
    const int t = threadIdx.x;
    if (t == 0) nr = 0;
    __syncthreads();

    const int r = blockIdx.x * 128 + t;
    const int b = r / Sc, s = r % Sc;
    if (!g_filled[r] && s < seq_len[b]) rows[atomicAdd(&nr, 1)] = r;
    __syncthreads();

    for (int i = 0; i < nr; i++) {
        const int rr = rows[i];
        const int bb = rr / Sc;
        const int nf = g_nfill[bb];
        const float inv = 1.0f / (float)(nf > 0 ? nf : 1);
        float4 v;
        v.x = f2tf_f(g_avgsum[bb * Dc + t * 4 + 0] * inv);
        v.y = f2tf_f(g_avgsum[bb * Dc + t * 4 + 1] * inv);
        v.z = f2tf_f(g_avgsum[bb * Dc + t * 4 + 2] * inv);
        v.w = f2tf_f(g_avgsum[bb * Dc + t * 4 + 3] * inv);
        reinterpret_cast<float4*>(g_pooled)[(size_t)rr * (Dc / 4) + t] = v;
    }
}

// ---------------- kernel 3: GEMM out = pooled @ W^T + bias (tf32 mma) ------
// M=16384, N=512, K=512. BM=BN=128, BK=16, 3-stage cp.async, ONE sync/iter.
// 16 warps (512 thr), warp tile 32x32, reg-capped for 2 CTAs/SM (32 warps).
#define BM 128
#define BN 128
#define BK 16
#define PADK 24     // conflict-free for LDS.64 fragment reads (verified per-phase)
#define STG 3
#define GEMM_THREADS 512
#define SMEM_BYTES (STG * (BM + BN) * PADK * 4)

__global__ __launch_bounds__(GEMM_THREADS, 2)
void gemm_kernel(const float* __restrict__ bias, float* __restrict__ out) {
    extern __shared__ float smem[];
    float* AsBase = smem;                         // [STG][BM][PADK]
    float* BsBase = smem + STG * BM * PADK;       // [STG][BN][PADK]

    const int tid = threadIdx.x;
    const int bm = blockIdx.x, bn = blockIdx.y;

    const float* Aori = g_pooled + (size_t)bm * BM * Dc;
    const float* Bori = g_Wtf + (size_t)bn * BN * Dc;

    const int warp = tid >> 5, lane = tid & 31;
    const int wm = warp >> 2, wn = warp & 3;      // 4 x 4 warp grid
    const int m_off = wm * 32, n_off = wn * 32;   // 32x32 warp tile
    const int lr = lane >> 2, lc = lane & 3;

    float c[2][4][4];
#pragma unroll
    for (int mi = 0; mi < 2; mi++)
#pragma unroll
        for (int ni = 0; ni < 4; ni++)
#pragma unroll
            for (int j = 0; j < 4; j++) c[mi][ni][j] = 0.f;

    // A: 128 rows x 16 cols = 512 x 16B chunks; 512 threads -> 1 each. B same.
    const int ld_row = tid >> 2, ld_c4 = tid & 3;
    auto load_tile = [&](int kt, int st) {
        const int k0 = kt * BK;
        float* A = AsBase + st * BM * PADK;
        float* B = BsBase + st * BN * PADK;
        cp_async16cg(A + ld_row * PADK + ld_c4 * 4,
                     Aori + (size_t)ld_row * Dc + k0 + ld_c4 * 4);
        cp_async16cg(B + ld_row * PADK + ld_c4 * 4,
                     Bori + (size_t)ld_row * Dc + k0 + ld_c4 * 4);
        asm volatile("cp.async.commit_group;");
    };

    const int KT = Dc / BK;  // 32
    load_tile(0, 0);
    load_tile(1, 1);

    for (int kt = 0; kt < KT; kt++) {
        asm volatile("cp.async.wait_group 1;");
        __syncthreads();
        if (kt + 2 < KT) load_tile(kt + 2, (kt + 2) % STG);

        const float* A = AsBase + (kt % STG) * BM * PADK;
        const float* B = BsBase + (kt % STG) * BN * PADK;

#pragma unroll
        for (int ks = 0; ks < 2; ks++) {
            const int k0 = ks * 8 + 2 * lc;
            float2 alo[2], ahi[2], bv[4];
#pragma unroll
            for (int mi = 0; mi < 2; mi++) {
                const int r0 = m_off + mi * 16 + lr;
                alo[mi] = *reinterpret_cast<const float2*>(A + r0 * PADK + k0);
                ahi[mi] = *reinterpret_cast<const float2*>(A + (r0 + 8) * PADK + k0);
            }
#pragma unroll
            for (int ni = 0; ni < 4; ni++) {
                const int r0 = n_off + ni * 8 + lr;
                bv[ni] = *reinterpret_cast<const float2*>(B + r0 * PADK + k0);
            }
#pragma unroll
            for (int mi = 0; mi < 2; mi++)
#pragma unroll
                for (int ni = 0; ni < 4; ni++) {
                    MMA_TF32(c[mi][ni][0], c[mi][ni][1], c[mi][ni][2], c[mi][ni][3],
                             __float_as_uint(alo[mi].x), __float_as_uint(ahi[mi].x),
                             __float_as_uint(alo[mi].y), __float_as_uint(ahi[mi].y),
                             __float_as_uint(bv[ni].x), __float_as_uint(bv[ni].y));
                }
        }
        // no trailing sync — STG=3: the stage written by iteration kt+1's load
        // ((kt+3)%3) was consumed in iteration kt-1, ordered by the top barrier.
    }

    // epilogue: + bias, write fp32
    const int row_base = bm * BM + m_off;
    const int col_base = bn * BN + n_off;
#pragma unroll
    for (int mi = 0; mi < 2; mi++) {
#pragma unroll
        for (int ni = 0; ni < 4; ni++) {
            int r0 = row_base + mi * 16 + lr;
            int col = col_base + ni * 8 + 2 * lc;
            float b0 = bias[col], b1 = bias[col + 1];
            float2 v0 = make_float2(c[mi][ni][0] + b0, c[mi][ni][1] + b1);
            float2 v1 = make_float2(c[mi][ni][2] + b0, c[mi][ni][3] + b1);
            *reinterpret_cast<float2*>(out + (size_t)r0 * OUTc + col) = v0;
            *reinterpret_cast<float2*>(out + (size_t)(r0 + 8) * OUTc + col) = v1;
        }
    }
}

// ---------------- launcher -------------------------------------------------
extern "C" void kernel_launch(void* const* d_in, const int* in_sizes, int n_in,
                              void* d_out, int out_size) {
    const float* rep     = (const float*)d_in[0];
    const int*   ids     = (const int*)d_in[1];
    const int*   aa_len  = (const int*)d_in[2];
    const int*   seq_len = (const int*)d_in[3];
    const float* Wm      = (const float*)d_in[4];
    const float* bias    = (const float*)d_in[5];
    float*       out     = (float*)d_out;

    static bool attr_done = false;
    if (!attr_done) {
        cudaFuncSetAttribute(gemm_kernel, cudaFuncAttributeMaxDynamicSharedMemorySize,
                             SMEM_BYTES);
        attr_done = true;
    }

    prep_kernel<<<(OUTc * Dc + 255) / 256, 256>>>(Wm);
    pool_kernel<<<Bc * (Sc / CH), 128>>>(rep, ids, aa_len, seq_len);
    fill_kernel<<<Bc * Sc / 128, 128>>>(seq_len);
    dim3 grid(Bc * Sc / BM, OUTc / BN);
    gemm_kernel<<<grid, GEMM_THREADS, SMEM_BYTES>>>(bias, out);
}

// round 17
// speedup vs baseline: 3.9380x; 1.2753x over previous
#include <cuda_runtime.h>
#include <cuda_fp16.h>
#include <cstdint>

// Problem shape (fixed by the dataset)
#define Bc   8
#define Ac   16384
#define Sc   2048
#define Dc   512
#define OUTc 512
#define CH   16      // residues per pool block

// K-dimension permutation for fp16 m16n8k16 fragments.
// k = 16g + 8h + 2j + e  ->  np = 16g + 4j + 2h + e
// so the fragment quad (2j, 2j+1, 8+2j, 8+2j+1) is 4 contiguous halves = LDS.64.
__host__ __device__ __forceinline__ int kperm16(int k) {
    int g = k >> 4, r = k & 15;
    int h = r >> 3, j = (r >> 1) & 3, e = r & 1;
    return (g << 4) | (j << 2) | (h << 1) | e;
}

// ---------------- scratch (device globals; no allocation allowed) ----------
__device__ __half g_pooledh[Bc * Sc * Dc];  // 16 MB pooled [B,S,D], fp16, k-permuted
__device__ __half g_Wh[OUTc * Dc];          // W fp16, k-permuted
__device__ float  g_avgsum[Bc * Dc];        // per-protein sums (k-permuted space)
__device__ int    g_filled[Bc * Sc];
__device__ int    g_nfill[Bc];

// ---------------- helpers --------------------------------------------------
#define MMA_F16(c0, c1, c2, c3, a0, a1, a2, a3, b0, b1)                       \
    asm volatile(                                                             \
        "mma.sync.aligned.m16n8k16.row.col.f32.f16.f16.f32 "                  \
        "{%0,%1,%2,%3}, {%4,%5,%6,%7}, {%8,%9}, {%0,%1,%2,%3};"               \
        : "+f"(c0), "+f"(c1), "+f"(c2), "+f"(c3)                              \
        : "r"(a0), "r"(a1), "r"(a2), "r"(a3), "r"(b0), "r"(b1))

__device__ __forceinline__ void cp_async16cg(void* smem_dst, const void* gmem_src) {
    uint32_t dst = (uint32_t)__cvta_generic_to_shared(smem_dst);
    asm volatile("cp.async.cg.shared.global [%0], [%1], 16;" ::"r"(dst), "l"(gmem_src));
}

// ---------------- kernel 0: zero accumulators + convert W to fp16 ----------
__global__ void prep_kernel(const float* __restrict__ W) {
    int i = blockIdx.x * 256 + threadIdx.x;
    if (i < OUTc * Dc) {
        int o = i >> 9, k = i & 511;
        g_Wh[(o << 9) + kperm16(k)] = __float2half_rn(W[i]);
    }
    if (i < Bc * Dc) g_avgsum[i] = 0.0f;
    if (i < Bc) g_nfill[i] = 0;
}

// ---------------- kernel 1: fused segment-mean pooling + avg accumulation --
__global__ void pool_kernel(const float* __restrict__ rep,
                            const int* __restrict__ ids,
                            const int* __restrict__ aa_len,
                            const int* __restrict__ seq_len) {
    const int blk = blockIdx.x;
    const int b = blk / (Sc / CH);
    const int s0 = (blk % (Sc / CH)) * CH;
    const int L = aa_len[b];
    const int SL = seq_len[b];
    const int* p = ids + b * Ac;

    __shared__ int bound[CH + 1];
    const int t = threadIdx.x;  // 128 threads x 4 cols = 512 cols

    if (t <= CH) {
        int target = s0 + t;
        int lo = 0, hi = L;
        while (lo < hi) { int mid = (lo + hi) >> 1; if (p[mid] < target) lo = mid + 1; else hi = mid; }
        bound[t] = lo;
    }
    __syncthreads();

    // thread t owns old cols 4t..4t+3, all in 16-group (t>>2).
    // old (4t,4t+1) -> permuted (pos0,pos0+1); (4t+2,4t+3) -> (pos0+4,pos0+5)
    const int m = t & 3;
    const int base = ((m & 1) << 3) | ((m >> 1) << 1);  // m:0,1,2,3 -> 0,8,2,10
    const int pos0 = ((t >> 2) << 4) + base;
    const int pos1 = pos0 + 4;

    const float4* basep = reinterpret_cast<const float4*>(rep) + (size_t)b * Ac * (Dc / 4);
    float4 avg = make_float4(0.f, 0.f, 0.f, 0.f);
    int nf_local = 0;

#pragma unroll 1
    for (int i = 0; i < CH; i++) {
        const int st = bound[i], en = bound[i + 1];
        float4 acc = make_float4(0.f, 0.f, 0.f, 0.f);
        int a = st;
        for (; a + 3 < en; a += 4) {
            float4 v0 = basep[(size_t)(a + 0) * (Dc / 4) + t];
            float4 v1 = basep[(size_t)(a + 1) * (Dc / 4) + t];
            float4 v2 = basep[(size_t)(a + 2) * (Dc / 4) + t];
            float4 v3 = basep[(size_t)(a + 3) * (Dc / 4) + t];
            acc.x += (v0.x + v1.x) + (v2.x + v3.x);
            acc.y += (v0.y + v1.y) + (v2.y + v3.y);
            acc.z += (v0.z + v1.z) + (v2.z + v3.z);
            acc.w += (v0.w + v1.w) + (v2.w + v3.w);
        }
        for (; a < en; a++) {
            float4 v0 = basep[(size_t)a * (Dc / 4) + t];
            acc.x += v0.x; acc.y += v0.y; acc.z += v0.z; acc.w += v0.w;
        }
        const int cnt = en - st;
        const float inv = 1.0f / (float)(cnt > 0 ? cnt : 1);
        const __half2 h01 = __floats2half2_rn(acc.x * inv, acc.y * inv);
        const __half2 h23 = __floats2half2_rn(acc.z * inv, acc.w * inv);
        const float q0 = __low2float(h01), q1 = __high2float(h01);
        const float q2 = __low2float(h23), q3 = __high2float(h23);

        const int row = b * Sc + s0 + i;
        __half2* ph = reinterpret_cast<__half2*>(g_pooledh + (size_t)row * Dc);
        ph[pos0 >> 1] = h01;
        ph[pos1 >> 1] = h23;

        const bool fill = (cnt > 0) && (s0 + i < SL);
        if (fill) {
            avg.x += q0; avg.y += q1; avg.z += q2; avg.w += q3;
            nf_local++;
        }
        if (t == 0) g_filled[row] = fill ? 1 : 0;
    }

    atomicAdd(&g_avgsum[b * Dc + pos0 + 0], avg.x);
    atomicAdd(&g_avgsum[b * Dc + pos0 + 1], avg.y);
    atomicAdd(&g_avgsum[b * Dc + pos1 + 0], avg.z);
    atomicAdd(&g_avgsum[b * Dc + pos1 + 1], avg.w);
    if (t == 0) atomicAdd(&g_nfill[b], nf_local);
}

// ---------------- kernel 2: fill unfilled in-range rows with protein avg ---
// avgsum and pooled share the same permuted col space -> linear copy.
__global__ void fill_kernel(const int* __restrict__ seq_len) {
    __shared__ int rows[128];
    __shared__ int nr;
    const int t = threadIdx.x;
    if (t == 0) nr = 0;
    __syncthreads();

    const int r = blockIdx.x * 128 + t;
    const int b = r / Sc, s = r % Sc;
    if (!g_filled[r] && s < seq_len[b]) rows[atomicAdd(&nr, 1)] = r;
    __syncthreads();

    for (int i = 0; i < nr; i++) {
        const int rr = rows[i];
        const int bb = rr / Sc;
        const int nf = g_nfill[bb];
        const float inv = 1.0f / (float)(nf > 0 ? nf : 1);
        const float* av = g_avgsum + bb * Dc + 4 * t;
        __half2 v01 = __floats2half2_rn(av[0] * inv, av[1] * inv);
        __half2 v23 = __floats2half2_rn(av[2] * inv, av[3] * inv);
        __half2* ph = reinterpret_cast<__half2*>(g_pooledh + (size_t)rr * Dc);
        ph[2 * t + 0] = v01;
        ph[2 * t + 1] = v23;
    }
}

// ---------------- kernel 3: GEMM out = pooled @ W^T + bias (fp16 mma) ------
// M=16384, N=512, K=512. BM=BN=128, BK=32 halves, 3-stage cp.async.
// 16 warps (512 thr), warp tile 32x32, m16n8k16, fp32 accum.
#define BM 128
#define BN 128
#define BKH 32      // halves per K-tile
#define WROW 24     // words (uint32) per smem row: 16 data + 8 pad
                    // fragment bank-pair = (12*lr + lc) mod 16 -> conflict-free
#define STG 3
#define GEMM_THREADS 512
#define SMEM_BYTES (STG * (BM + BN) * WROW * 4)

__global__ __launch_bounds__(GEMM_THREADS, 2)
void gemm_kernel(const float* __restrict__ bias, float* __restrict__ out) {
    extern __shared__ uint32_t smem[];
    uint32_t* AsBase = smem;                         // [STG][BM][WROW]
    uint32_t* BsBase = smem + STG * BM * WROW;       // [STG][BN][WROW]

    const int tid = threadIdx.x;
    const int bm = blockIdx.x, bn = blockIdx.y;

    const __half* Aori = g_pooledh + (size_t)bm * BM * Dc;
    const __half* Bori = g_Wh + (size_t)bn * BN * Dc;

    const int warp = tid >> 5, lane = tid & 31;
    const int wm = warp >> 2, wn = warp & 3;      // 4 x 4 warp grid
    const int m_off = wm * 32, n_off = wn * 32;   // 32x32 warp tile
    const int lr = lane >> 2, lc = lane & 3;

    float c[2][4][4];
#pragma unroll
    for (int mi = 0; mi < 2; mi++)
#pragma unroll
        for (int ni = 0; ni < 4; ni++)
#pragma unroll
            for (int j = 0; j < 4; j++) c[mi][ni][j] = 0.f;

    // A: 128 rows x 32 halves = 64B/row = 4 x 16B chunks -> 512 chunks,
    // 512 threads -> 1 each. B identical.
    const int ld_row = tid >> 2, ld_c4 = tid & 3;
    auto load_tile = [&](int kt, int st) {
        const int k0 = kt * BKH;
        uint32_t* A = AsBase + st * BM * WROW;
        uint32_t* B = BsBase + st * BN * WROW;
        cp_async16cg(A + ld_row * WROW + ld_c4 * 4,
                     Aori + (size_t)ld_row * Dc + k0 + ld_c4 * 8);
        cp_async16cg(B + ld_row * WROW + ld_c4 * 4,
                     Bori + (size_t)ld_row * Dc + k0 + ld_c4 * 8);
        asm volatile("cp.async.commit_group;");
    };

    const int KT = Dc / BKH;  // 16
    load_tile(0, 0);
    load_tile(1, 1);

    for (int kt = 0; kt < KT; kt++) {
        asm volatile("cp.async.wait_group 1;");
        __syncthreads();
        if (kt + 2 < KT) load_tile(kt + 2, (kt + 2) % STG);

        const uint32_t* A = AsBase + (kt % STG) * BM * WROW;
        const uint32_t* B = BsBase + (kt % STG) * BN * WROW;

#pragma unroll
        for (int g = 0; g < 2; g++) {             // two k16 halves of BKH=32
            const int k0 = g * 8 + 2 * lc;        // word offset within row
            uint2 alo[2], ahi[2], bv[4];
#pragma unroll
            for (int mi = 0; mi < 2; mi++) {
                const int r0 = m_off + mi * 16 + lr;
                alo[mi] = *reinterpret_cast<const uint2*>(A + r0 * WROW + k0);
                ahi[mi] = *reinterpret_cast<const uint2*>(A + (r0 + 8) * WROW + k0);
            }
#pragma unroll
            for (int ni = 0; ni < 4; ni++) {
                const int r0 = n_off + ni * 8 + lr;
                bv[ni] = *reinterpret_cast<const uint2*>(B + r0 * WROW + k0);
            }
#pragma unroll
            for (int mi = 0; mi < 2; mi++)
#pragma unroll
                for (int ni = 0; ni < 4; ni++) {
                    MMA_F16(c[mi][ni][0], c[mi][ni][1], c[mi][ni][2], c[mi][ni][3],
                            alo[mi].x, ahi[mi].x, alo[mi].y, ahi[mi].y,
                            bv[ni].x, bv[ni].y);
                }
        }
        // no trailing sync — STG=3: the stage written by iteration kt+1's load
        // ((kt+3)%3) was consumed in iteration kt-1, ordered by the top barrier.
    }

    // epilogue: + bias, write fp32 (D fragment layout identical to k8 case)
    const int row_base = bm * BM + m_off;
    const int col_base = bn * BN + n_off;
#pragma unroll
    for (int mi = 0; mi < 2; mi++) {
#pragma unroll
        for (int ni = 0; ni < 4; ni++) {
            int r0 = row_base + mi * 16 + lr;
            int col = col_base + ni * 8 + 2 * lc;
            float b0 = bias[col], b1 = bias[col + 1];
            float2 v0 = make_float2(c[mi][ni][0] + b0, c[mi][ni][1] + b1);
            float2 v1 = make_float2(c[mi][ni][2] + b0, c[mi][ni][3] + b1);
            *reinterpret_cast<float2*>(out + (size_t)r0 * OUTc + col) = v0;
            *reinterpret_cast<float2*>(out + (size_t)(r0 + 8) * OUTc + col) = v1;
        }
    }
}

// ---------------- launcher -------------------------------------------------
extern "C" void kernel_launch(void* const* d_in, const int* in_sizes, int n_in,
                              void* d_out, int out_size) {
    const float* rep     = (const float*)d_in[0];
    const int*   ids     = (const int*)d_in[1];
    const int*   aa_len  = (const int*)d_in[2];
    const int*   seq_len = (const int*)d_in[3];
    const float* Wm      = (const float*)d_in[4];
    const float* bias    = (const float*)d_in[5];
    float*       out     = (float*)d_out;

    static bool attr_done = false;
    if (!attr_done) {
        cudaFuncSetAttribute(gemm_kernel, cudaFuncAttributeMaxDynamicSharedMemorySize,
                             SMEM_BYTES);
        attr_done = true;
    }

    prep_kernel<<<(OUTc * Dc + 255) / 256, 256>>>(Wm);
    pool_kernel<<<Bc * (Sc / CH), 128>>>(rep, ids, aa_len, seq_len);
    fill_kernel<<<Bc * Sc / 128, 128>>>(seq_len);
    dim3 grid(Bc * Sc / BM, OUTc / BN);
    gemm_kernel<<<grid, GEMM_THREADS, SMEM_BYTES>>>(bias, out);
}